// round 2
// baseline (speedup 1.0000x reference)
#include <cuda_runtime.h>
#include <cuda_bf16.h>

#define N_NODES 50000
#define HYPER_DIM 128
#define NNZ 800000
#define LEAKY 0.2f
#define LN_EPS 1e-5f

// Scratch (allocation-free): three 25.6 MB feature matrices.
__device__ float g_ht[(size_t)N_NODES * HYPER_DIM];
__device__ float g_h[(size_t)N_NODES * HYPER_DIM];
__device__ float g_embs[(size_t)N_NODES * HYPER_DIM];

// ---------------------------------------------------------------------------
// Zero-fill: float4 stores
// ---------------------------------------------------------------------------
__global__ void zero_kernel(float4* __restrict__ p, int n4) {
    int i = blockIdx.x * blockDim.x + threadIdx.x;
    if (i < n4) p[i] = make_float4(0.f, 0.f, 0.f, 0.f);
}

// ---------------------------------------------------------------------------
// Edge-parallel scatter SpMM:  out[dst[e]] += vals[e] * x[src[e]]
// One warp per edge; lane l handles features [4l, 4l+4).
// atomicAdd return unused -> RED.E.ADD.F32 (no-return) in SASS.
// ---------------------------------------------------------------------------
__global__ void spmm_atomic_kernel(const int* __restrict__ src,
                                   const int* __restrict__ dst,
                                   const float* __restrict__ vals,
                                   const float* __restrict__ x,
                                   float* __restrict__ out) {
    int gw = (blockIdx.x * blockDim.x + threadIdx.x) >> 5;
    if (gw >= NNZ) return;
    int lane = threadIdx.x & 31;

    int s = src[gw];
    int d = dst[gw];
    float v = vals[gw];

    const float4* xr = reinterpret_cast<const float4*>(x + (size_t)s * HYPER_DIM);
    float4 a = xr[lane];

    float* o = out + (size_t)d * HYPER_DIM + lane * 4;
    atomicAdd(o + 0, v * a.x);
    atomicAdd(o + 1, v * a.y);
    atomicAdd(o + 2, v * a.z);
    atomicAdd(o + 3, v * a.w);
}

// ---------------------------------------------------------------------------
// Fused (optional leaky) + LayerNorm + residual. One warp per node.
// ---------------------------------------------------------------------------
template <int DO_LEAKY>
__global__ void ln_res_kernel(const float* __restrict__ h,
                              const float* __restrict__ gamma,
                              const float* __restrict__ beta,
                              const float* __restrict__ res,
                              float* __restrict__ out) {
    int n = (blockIdx.x * blockDim.x + threadIdx.x) >> 5;
    if (n >= N_NODES) return;
    int lane = threadIdx.x & 31;

    float4 a = reinterpret_cast<const float4*>(h + (size_t)n * HYPER_DIM)[lane];
    if (DO_LEAKY) {
        a.x = a.x >= 0.f ? a.x : LEAKY * a.x;
        a.y = a.y >= 0.f ? a.y : LEAKY * a.y;
        a.z = a.z >= 0.f ? a.z : LEAKY * a.z;
        a.w = a.w >= 0.f ? a.w : LEAKY * a.w;
    }

    float s = a.x + a.y + a.z + a.w;
    #pragma unroll
    for (int m = 16; m > 0; m >>= 1) s += __shfl_xor_sync(0xFFFFFFFFu, s, m);
    float mu = s * (1.f / HYPER_DIM);

    float dx = a.x - mu, dy = a.y - mu, dz = a.z - mu, dw = a.w - mu;
    float sq = dx * dx + dy * dy + dz * dz + dw * dw;
    #pragma unroll
    for (int m = 16; m > 0; m >>= 1) sq += __shfl_xor_sync(0xFFFFFFFFu, sq, m);
    float rstd = rsqrtf(sq * (1.f / HYPER_DIM) + LN_EPS);

    float4 g = reinterpret_cast<const float4*>(gamma)[lane];
    float4 b = reinterpret_cast<const float4*>(beta)[lane];
    float4 r = reinterpret_cast<const float4*>(res + (size_t)n * HYPER_DIM)[lane];

    float4 o;
    o.x = dx * rstd * g.x + b.x + r.x;
    o.y = dy * rstd * g.y + b.y + r.y;
    o.z = dz * rstd * g.z + b.z + r.z;
    o.w = dw * rstd * g.w + b.w + r.w;
    reinterpret_cast<float4*>(out + (size_t)n * HYPER_DIM)[lane] = o;
}

// ---------------------------------------------------------------------------
// Launch
// ---------------------------------------------------------------------------
extern "C" void kernel_launch(void* const* d_in, const int* in_sizes, int n_in,
                              void* d_out, int out_size) {
    const float* ego   = (const float*)d_in[0];
    const float* vals  = (const float*)d_in[1];
    const float* gamma = (const float*)d_in[2];   // [2, 128]
    const float* beta  = (const float*)d_in[3];   // [2, 128]
    const int*   rows  = (const int*)d_in[4];
    const int*   cols  = (const int*)d_in[5];
    float* out = (float*)d_out;

    float* ht; cudaGetSymbolAddress((void**)&ht, g_ht);
    float* h;  cudaGetSymbolAddress((void**)&h,  g_h);
    float* em; cudaGetSymbolAddress((void**)&em, g_embs);

    const int n4 = N_NODES * HYPER_DIM / 4;                // 1.6M float4s
    const int zgrid = (n4 + 255) / 256;
    const int sgrid = (NNZ * 32 + 255) / 256;              // warp per edge
    const int lgrid = (N_NODES * 32 + 255) / 256;          // warp per node

    // ---- Layer 0 ----
    zero_kernel<<<zgrid, 256>>>((float4*)ht, n4);
    //  ht[cols[e]] += vals[e] * ego[rows[e]]
    spmm_atomic_kernel<<<sgrid, 256>>>(rows, cols, vals, ego, ht);
    zero_kernel<<<zgrid, 256>>>((float4*)h, n4);
    //  h[rows[e]] += vals[e] * ht[cols[e]]
    spmm_atomic_kernel<<<sgrid, 256>>>(cols, rows, vals, ht, h);
    //  embs = LN(leaky(h)) * gamma0 + beta0 + ego
    ln_res_kernel<1><<<lgrid, 256>>>(h, gamma, beta, ego, em);

    // ---- Layer 1 ----
    zero_kernel<<<zgrid, 256>>>((float4*)ht, n4);
    spmm_atomic_kernel<<<sgrid, 256>>>(rows, cols, vals, em, ht);
    zero_kernel<<<zgrid, 256>>>((float4*)h, n4);
    spmm_atomic_kernel<<<sgrid, 256>>>(cols, rows, vals, ht, h);
    //  out = LN(h) * gamma1 + beta1 + ego   (no leaky on last layer)
    ln_res_kernel<0><<<lgrid, 256>>>(h, gamma + HYPER_DIM, beta + HYPER_DIM, ego, out);
}

// round 5
// speedup vs baseline: 3.4214x; 3.4214x over previous
#include <cuda_runtime.h>
#include <cuda_bf16.h>

#define N_NODES 50000
#define HYPER_DIM 128
#define NNZ 800000
#define LEAKY 0.2f
#define LN_EPS 1e-5f
#define FULL 0xFFFFFFFFu

// ---------------------------------------------------------------------------
// Scratch (allocation-free __device__ globals)
// ---------------------------------------------------------------------------
__device__ int g_cntA[N_NODES + 1];     // per-col edge counts
__device__ int g_cntB[N_NODES + 1];     // per-row edge counts
__device__ int g_ptrA[N_NODES + 1];     // CSR ptr, orientation A (sorted by col)
__device__ int g_ptrB[N_NODES + 1];     // CSR ptr, orientation B (sorted by row)
__device__ int g_workA[N_NODES + 1];    // running offsets for scatter
__device__ int g_workB[N_NODES + 1];
__device__ int2 g_edgeA[NNZ];           // {neighbor=row, val} sorted by col
__device__ int2 g_edgeB[NNZ];           // {neighbor=col, val} sorted by row
__device__ float g_ht[(size_t)N_NODES * HYPER_DIM];
__device__ float g_embs[(size_t)N_NODES * HYPER_DIM];

// ---------------------------------------------------------------------------
// 1. zero both histograms
// ---------------------------------------------------------------------------
__global__ void zero_cnt_kernel() {
    int i = blockIdx.x * blockDim.x + threadIdx.x;
    if (i <= N_NODES) { g_cntA[i] = 0; g_cntB[i] = 0; }
}

// ---------------------------------------------------------------------------
// 2. histogram of edge endpoints
// ---------------------------------------------------------------------------
__global__ void hist_kernel(const int* __restrict__ rows,
                            const int* __restrict__ cols) {
    int e = blockIdx.x * blockDim.x + threadIdx.x;
    if (e >= NNZ) return;
    atomicAdd(&g_cntA[cols[e]], 1);
    atomicAdd(&g_cntB[rows[e]], 1);
}

// ---------------------------------------------------------------------------
// 3. exclusive scan (single block per orientation; blockIdx picks which)
// ---------------------------------------------------------------------------
__global__ void scan_kernel() {
    const int* cnt = (blockIdx.x == 0) ? g_cntA : g_cntB;
    int* ptr       = (blockIdx.x == 0) ? g_ptrA : g_ptrB;
    int* work      = (blockIdx.x == 0) ? g_workA : g_workB;

    __shared__ int partial[1024];
    const int CH = (N_NODES + 1023) / 1024;   // 49
    int t = threadIdx.x;
    int begin = t * CH;

    int sum = 0;
    for (int i = 0; i < CH; i++) {
        int g = begin + i;
        if (g < N_NODES) sum += cnt[g];
    }
    partial[t] = sum;
    __syncthreads();

    // Hillis–Steele inclusive scan over 1024 partials
    for (int off = 1; off < 1024; off <<= 1) {
        int v = partial[t];
        int add = (t >= off) ? partial[t - off] : 0;
        __syncthreads();
        partial[t] = v + add;
        __syncthreads();
    }

    int run = (t == 0) ? 0 : partial[t - 1];
    for (int i = 0; i < CH; i++) {
        int g = begin + i;
        if (g < N_NODES) {
            ptr[g] = run;
            work[g] = run;
            run += cnt[g];
        }
    }
    if (t == 1023) { ptr[N_NODES] = partial[1023]; work[N_NODES] = partial[1023]; }
}

// ---------------------------------------------------------------------------
// 4. scatter edges into both CSR orientations
// ---------------------------------------------------------------------------
__global__ void scatter_kernel(const int* __restrict__ rows,
                               const int* __restrict__ cols,
                               const float* __restrict__ vals) {
    int e = blockIdx.x * blockDim.x + threadIdx.x;
    if (e >= NNZ) return;
    int r = rows[e], c = cols[e];
    int v = __float_as_int(vals[e]);
    int pa = atomicAdd(&g_workA[c], 1);
    g_edgeA[pa] = make_int2(r, v);
    int pb = atomicAdd(&g_workB[r], 1);
    g_edgeB[pb] = make_int2(c, v);
}

// ---------------------------------------------------------------------------
// 5. gather SpMM: warp per node, register accumulator, optional fused
//    leaky + LayerNorm + residual epilogue.
// ---------------------------------------------------------------------------
template <int FUSE_LN, int DO_LEAKY>
__global__ void gather_spmm_kernel(const int* __restrict__ ptr,
                                   const int2* __restrict__ edge,
                                   const float* __restrict__ x,
                                   const float* __restrict__ gamma,
                                   const float* __restrict__ beta,
                                   const float* __restrict__ res,
                                   float* __restrict__ out) {
    int n = (blockIdx.x * blockDim.x + threadIdx.x) >> 5;
    if (n >= N_NODES) return;
    int lane = threadIdx.x & 31;

    int start = ptr[n];
    int end   = ptr[n + 1];

    const float4* xr = reinterpret_cast<const float4*>(x);
    float4 acc = make_float4(0.f, 0.f, 0.f, 0.f);

    for (int base = start; base < end; base += 32) {
        int k = base + lane;
        int2 ev = (k < end) ? edge[k] : make_int2(0, 0);
        int cnt = min(32, end - base);
        #pragma unroll 8
        for (int t = 0; t < cnt; t++) {
            int jj   = __shfl_sync(FULL, ev.x, t);
            float vv = __int_as_float(__shfl_sync(FULL, ev.y, t));
            float4 a = xr[(size_t)jj * 32 + lane];
            acc.x += vv * a.x;
            acc.y += vv * a.y;
            acc.z += vv * a.z;
            acc.w += vv * a.w;
        }
    }

    if (FUSE_LN) {
        if (DO_LEAKY) {
            acc.x = acc.x >= 0.f ? acc.x : LEAKY * acc.x;
            acc.y = acc.y >= 0.f ? acc.y : LEAKY * acc.y;
            acc.z = acc.z >= 0.f ? acc.z : LEAKY * acc.z;
            acc.w = acc.w >= 0.f ? acc.w : LEAKY * acc.w;
        }
        float s = acc.x + acc.y + acc.z + acc.w;
        #pragma unroll
        for (int m = 16; m > 0; m >>= 1) s += __shfl_xor_sync(FULL, s, m);
        float mu = s * (1.f / HYPER_DIM);

        float dx = acc.x - mu, dy = acc.y - mu, dz = acc.z - mu, dw = acc.w - mu;
        float sq = dx * dx + dy * dy + dz * dz + dw * dw;
        #pragma unroll
        for (int m = 16; m > 0; m >>= 1) sq += __shfl_xor_sync(FULL, sq, m);
        float rstd = rsqrtf(sq * (1.f / HYPER_DIM) + LN_EPS);

        float4 g = reinterpret_cast<const float4*>(gamma)[lane];
        float4 b = reinterpret_cast<const float4*>(beta)[lane];
        float4 r = reinterpret_cast<const float4*>(res + (size_t)n * HYPER_DIM)[lane];

        acc.x = dx * rstd * g.x + b.x + r.x;
        acc.y = dy * rstd * g.y + b.y + r.y;
        acc.z = dz * rstd * g.z + b.z + r.z;
        acc.w = dw * rstd * g.w + b.w + r.w;
    }

    reinterpret_cast<float4*>(out + (size_t)n * HYPER_DIM)[lane] = acc;
}

// ---------------------------------------------------------------------------
// Launch
// ---------------------------------------------------------------------------
extern "C" void kernel_launch(void* const* d_in, const int* in_sizes, int n_in,
                              void* d_out, int out_size) {
    const float* ego   = (const float*)d_in[0];
    const float* vals  = (const float*)d_in[1];
    const float* gamma = (const float*)d_in[2];   // [2, 128]
    const float* beta  = (const float*)d_in[3];   // [2, 128]
    const int*   rows  = (const int*)d_in[4];
    const int*   cols  = (const int*)d_in[5];
    float* out = (float*)d_out;

    float* ht; cudaGetSymbolAddress((void**)&ht, g_ht);
    float* em; cudaGetSymbolAddress((void**)&em, g_embs);
    int *ptrA, *ptrB; int2 *edgeA, *edgeB;
    cudaGetSymbolAddress((void**)&ptrA, g_ptrA);
    cudaGetSymbolAddress((void**)&ptrB, g_ptrB);
    cudaGetSymbolAddress((void**)&edgeA, g_edgeA);
    cudaGetSymbolAddress((void**)&edgeB, g_edgeB);

    const int egrid = (NNZ + 255) / 256;
    const int ngrid = (N_NODES * 32 + 255) / 256;   // warp per node

    // ---- CSR build (both orientations) ----
    zero_cnt_kernel<<<(N_NODES + 256) / 256, 256>>>();
    hist_kernel<<<egrid, 256>>>(rows, cols);
    scan_kernel<<<2, 1024>>>();
    scatter_kernel<<<egrid, 256>>>(rows, cols, vals);

    // ---- Layer 0 ----
    //  ht[c] = sum_e v * ego[r]          (orientation A)
    gather_spmm_kernel<0, 0><<<ngrid, 256>>>(ptrA, edgeA, ego,
                                             nullptr, nullptr, nullptr, ht);
    //  embs = LN(leaky(B @ ht)) * g0 + b0 + ego
    gather_spmm_kernel<1, 1><<<ngrid, 256>>>(ptrB, edgeB, ht,
                                             gamma, beta, ego, em);

    // ---- Layer 1 ----
    gather_spmm_kernel<0, 0><<<ngrid, 256>>>(ptrA, edgeA, em,
                                             nullptr, nullptr, nullptr, ht);
    //  out = LN(B @ ht) * g1 + b1 + ego   (no leaky on last layer)
    gather_spmm_kernel<1, 0><<<ngrid, 256>>>(ptrB, edgeB, ht,
                                             gamma + HYPER_DIM, beta + HYPER_DIM,
                                             ego, out);
}